// round 3
// baseline (speedup 1.0000x reference)
#include <cuda_runtime.h>
#include <cuda_fp16.h>

#define N_NODES 50000
#define D 128
#define E_MAX 800000

// ---------------- device scratch (no allocation allowed) ----------------
__device__ float  g_y[(size_t)N_NODES * D];    // gather outputs (fp32 activations)
__device__ __half g_z[(size_t)N_NODES * D];    // GEMM outputs (fp16, gathered operand)
__device__ int    g_is64;
__device__ int    g_src[E_MAX];
__device__ int    g_dst[E_MAX];
__device__ int    g_perm[E_MAX];               // CSR: src ids grouped by dst
__device__ int    g_deg[N_NODES];
__device__ int    g_off[N_NODES];
__device__ int    g_cur[N_NODES];
__device__ int    g_bsum[256];

// ---------------- f32x2 packed-math helpers (SASS FFMA2 path) ----------------
__device__ __forceinline__ unsigned long long pack2(float a, float b) {
    unsigned long long r;
    asm("mov.b64 %0, {%1, %2};" : "=l"(r) : "f"(a), "f"(b));
    return r;
}
__device__ __forceinline__ void fma2(unsigned long long& d, unsigned long long a,
                                     unsigned long long b) {
    asm("fma.rn.f32x2 %0, %1, %2, %0;" : "+l"(d) : "l"(a), "l"(b));
}
__device__ __forceinline__ float2 unpack2(unsigned long long v) {
    float2 r;
    asm("mov.b64 {%0, %1}, %2;" : "=f"(r.x), "=f"(r.y) : "l"(v));
    return r;
}

// ---------------- dtype detection for edge_index ----------------
__global__ void detect_kernel(const void* __restrict__ ei) {
    if (blockIdx.x == 0 && threadIdx.x == 0) {
        const long long* p = (const long long*)ei;
        int ok = 1;
        #pragma unroll
        for (int i = 0; i < 32; i++) {
            long long v = p[i];
            if (v < 0 || v >= N_NODES) ok = 0;
        }
        g_is64 = ok;
    }
}

// ---------------- CSR build ----------------
__global__ void convert_kernel(const void* __restrict__ ei, int E) {
    int i = blockIdx.x * blockDim.x + threadIdx.x;
    if (i >= E) return;
    int s, d;
    if (g_is64) {
        const long long* p = (const long long*)ei;
        s = (int)__ldg(p + i);
        d = (int)__ldg(p + E + i);
    } else {
        const int* p = (const int*)ei;
        s = __ldg(p + i);
        d = __ldg(p + E + i);
    }
    g_src[i] = s;
    g_dst[i] = d;
    atomicAdd(&g_deg[d], 1);
}

__global__ void scanA_kernel(int n) {
    __shared__ int sh[8];
    int t = threadIdx.x, i = blockIdx.x * 256 + t;
    int v = (i < n) ? g_deg[i] : 0;
    int lane = t & 31, w = t >> 5;
    int x = v;
    #pragma unroll
    for (int o = 1; o < 32; o <<= 1) {
        int y = __shfl_up_sync(0xFFFFFFFFu, x, o);
        if (lane >= o) x += y;
    }
    if (lane == 31) sh[w] = x;
    __syncthreads();
    if (t < 8) {
        int s = sh[t];
        #pragma unroll
        for (int o = 1; o < 8; o <<= 1) {
            int y = __shfl_up_sync(0xFFu, s, o);
            if (t >= o) s += y;
        }
        sh[t] = s;
    }
    __syncthreads();
    int incl = x + (w ? sh[w - 1] : 0);
    if (i < n) g_off[i] = incl - v;
    if (t == 255) g_bsum[blockIdx.x] = incl;
}

__global__ void scanB_kernel(int nb) {
    __shared__ int sh[8];
    int t = threadIdx.x;
    int v = (t < nb) ? g_bsum[t] : 0;
    int lane = t & 31, w = t >> 5;
    int x = v;
    #pragma unroll
    for (int o = 1; o < 32; o <<= 1) {
        int y = __shfl_up_sync(0xFFFFFFFFu, x, o);
        if (lane >= o) x += y;
    }
    if (lane == 31) sh[w] = x;
    __syncthreads();
    if (t < 8) {
        int s = sh[t];
        #pragma unroll
        for (int o = 1; o < 8; o <<= 1) {
            int y = __shfl_up_sync(0xFFu, s, o);
            if (t >= o) s += y;
        }
        sh[t] = s;
    }
    __syncthreads();
    int incl = x + (w ? sh[w - 1] : 0);
    if (t < nb) g_bsum[t] = incl - v;
}

__global__ void scanC_kernel(int n) {
    int i = blockIdx.x * blockDim.x + threadIdx.x;
    if (i >= n) return;
    int o = g_off[i] + g_bsum[i >> 8];
    g_off[i] = o;
    g_cur[i] = o;
}

__global__ void fill_kernel(int E) {
    int i = blockIdx.x * blockDim.x + threadIdx.x;
    if (i >= E) return;
    int d = g_dst[i];
    int p = atomicAdd(&g_cur[d], 1);
    g_perm[p] = g_src[i];
}

// ---------------- SGEMM: z = A @ W  (fp32 in, fp16 out, no bias/act) --------
// A: [N, 128]  W: [128, C]  BM=128, BN=C, BK=32, 256 threads, f32x2 packed FMA.
template <int C>
__global__ __launch_bounds__(256, 2)
void gemm_kernel(const float* __restrict__ A,
                 const float* __restrict__ W,
                 __half* __restrict__ out,
                 int N) {
    constexpr int BM  = 128;
    constexpr int BK  = 32;
    constexpr int NCG = C / 8;
    constexpr int NRG = 256 / NCG;
    constexpr int RPT = BM / NRG;

    __shared__ __align__(16) float As[BK][BM];
    __shared__ __align__(16) float Ws[BK][C];

    const int tid  = threadIdx.x;
    const int tx   = tid % NCG;
    const int ty   = tid / NCG;
    const int row0 = blockIdx.x * BM;

    unsigned long long acc[RPT][4];
    #pragma unroll
    for (int i = 0; i < RPT; i++)
        #pragma unroll
        for (int j = 0; j < 4; j++) acc[i][j] = 0ULL;

    for (int kb = 0; kb < D; kb += BK) {
        #pragma unroll
        for (int t = tid; t < BM * BK / 4; t += 256) {
            int r = t & 127, c4 = t >> 7;
            float4 v = make_float4(0.f, 0.f, 0.f, 0.f);
            if (row0 + r < N)
                v = __ldg((const float4*)(A + (size_t)(row0 + r) * D + kb) + c4);
            As[c4 * 4 + 0][r] = v.x;
            As[c4 * 4 + 1][r] = v.y;
            As[c4 * 4 + 2][r] = v.z;
            As[c4 * 4 + 3][r] = v.w;
        }
        #pragma unroll
        for (int t = tid; t < BK * C / 4; t += 256)
            ((float4*)Ws)[t] = __ldg((const float4*)(W + (size_t)kb * C) + t);
        __syncthreads();

        #pragma unroll
        for (int k = 0; k < BK; k++) {
            float av[RPT];
            {
                const float4* ap = (const float4*)&As[k][ty * RPT];
                float4 a0 = ap[0];
                av[0] = a0.x; av[1] = a0.y; av[2] = a0.z; av[3] = a0.w;
                if (RPT == 8) {
                    float4 a1 = ap[1];
                    av[4] = a1.x; av[5] = a1.y; av[6] = a1.z; av[7] = a1.w;
                }
            }
            unsigned long long adup[RPT];
            #pragma unroll
            for (int i = 0; i < RPT; i++) adup[i] = pack2(av[i], av[i]);

            const unsigned long long* wrow = (const unsigned long long*)&Ws[k][tx * 8];
            unsigned long long w2[4];
            #pragma unroll
            for (int j = 0; j < 4; j++) w2[j] = wrow[j];

            #pragma unroll
            for (int i = 0; i < RPT; i++)
                #pragma unroll
                for (int j = 0; j < 4; j++)
                    fma2(acc[i][j], adup[i], w2[j]);
        }
        __syncthreads();
    }

    // epilogue: fp32 -> fp16, 16B store of 8 cols per row
    #pragma unroll
    for (int i = 0; i < RPT; i++) {
        int r = row0 + ty * RPT + i;
        if (r >= N) continue;
        __align__(16) __half2 h[4];
        #pragma unroll
        for (int j = 0; j < 4; j++) {
            float2 p = unpack2(acc[i][j]);
            h[j] = __floats2half2_rn(p.x, p.y);
        }
        *(uint4*)(out + (size_t)r * C + tx * 8) = *(const uint4*)h;
    }
}

// ---------- gather (128-wide): y[i] = relu(z[i] + sum_j z[j] + b) -----------
// Warp per node; lane covers 4 halves (cols 4l..4l+3), fp32 accumulation.
__global__ void gather128_kernel(const __half* __restrict__ z,
                                 const float* __restrict__ bias,
                                 float* __restrict__ y, int N) {
    int node = (blockIdx.x * blockDim.x + threadIdx.x) >> 5;
    int lane = threadIdx.x & 31;
    if (node >= N) return;
    const uint2* z2 = (const uint2*)z;           // 4 halves per uint2
    int off = g_off[node];
    int deg = g_deg[node];

    uint2 u = __ldg(z2 + (size_t)node * 32 + lane);
    float2 a0 = __half22float2(*(const __half2*)&u.x);
    float2 a1 = __half22float2(*(const __half2*)&u.y);
    float4 acc = make_float4(a0.x, a0.y, a1.x, a1.y);

    for (int j0 = 0; j0 < deg; j0 += 32) {
        int idx = (j0 + lane < deg) ? g_perm[off + j0 + lane] : 0;
        int cnt = min(32, deg - j0);
        for (int t = 0; t < cnt; t++) {
            int s = __shfl_sync(0xFFFFFFFFu, idx, t);
            uint2 v = __ldg(z2 + (size_t)s * 32 + lane);
            float2 f0 = __half22float2(*(const __half2*)&v.x);
            float2 f1 = __half22float2(*(const __half2*)&v.y);
            acc.x += f0.x; acc.y += f0.y; acc.z += f1.x; acc.w += f1.y;
        }
    }
    float4 b = __ldg((const float4*)(bias) + lane);
    acc.x = fmaxf(acc.x + b.x, 0.f);
    acc.y = fmaxf(acc.y + b.y, 0.f);
    acc.z = fmaxf(acc.z + b.z, 0.f);
    acc.w = fmaxf(acc.w + b.w, 0.f);
    ((float4*)y)[(size_t)node * 32 + lane] = acc;
}

// ---------- gather (64-wide) + fused log_softmax -> d_out -------------------
// Warp per node; lane covers 2 halves (cols 2l, 2l+1).
__global__ void gather64_lsm_kernel(const __half* __restrict__ z,
                                    const float* __restrict__ bias,
                                    float* __restrict__ out, int N) {
    int node = (blockIdx.x * blockDim.x + threadIdx.x) >> 5;
    int lane = threadIdx.x & 31;
    if (node >= N) return;
    const unsigned int* z1 = (const unsigned int*)z;   // 1 half2 per uint
    int off = g_off[node];
    int deg = g_deg[node];

    unsigned int u = __ldg(z1 + (size_t)node * 32 + lane);
    float2 acc = __half22float2(*(const __half2*)&u);

    for (int j0 = 0; j0 < deg; j0 += 32) {
        int idx = (j0 + lane < deg) ? g_perm[off + j0 + lane] : 0;
        int cnt = min(32, deg - j0);
        for (int t = 0; t < cnt; t++) {
            int s = __shfl_sync(0xFFFFFFFFu, idx, t);
            unsigned int v = __ldg(z1 + (size_t)s * 32 + lane);
            float2 f = __half22float2(*(const __half2*)&v);
            acc.x += f.x; acc.y += f.y;
        }
    }
    float2 b = __ldg((const float2*)(bias) + lane);
    acc.x += b.x;
    acc.y += b.y;

    // log_softmax across the 64 values held by the warp
    float m = fmaxf(acc.x, acc.y);
    #pragma unroll
    for (int o = 16; o; o >>= 1) m = fmaxf(m, __shfl_xor_sync(0xFFFFFFFFu, m, o));
    float s = expf(acc.x - m) + expf(acc.y - m);
    #pragma unroll
    for (int o = 16; o; o >>= 1) s += __shfl_xor_sync(0xFFFFFFFFu, s, o);
    float l = m + logf(s);
    ((float2*)out)[(size_t)node * 32 + lane] = make_float2(acc.x - l, acc.y - l);
}

// ---------------- launch ----------------
extern "C" void kernel_launch(void* const* d_in, const int* in_sizes, int n_in,
                              void* d_out, int out_size) {
    const float* feature = (const float*)d_in[0];
    const void*  ei      = d_in[1];
    const float* W1      = (const float*)d_in[2];
    const float* b1      = (const float*)d_in[3];
    const float* Wh      = (const float*)d_in[4];
    const float* bh      = (const float*)d_in[5];
    const float* Wo      = (const float*)d_in[6];
    const float* bo      = (const float*)d_in[7];
    float* out = (float*)d_out;

    const int N = N_NODES;
    int E = in_sizes[1] / 2;
    if (E > E_MAX) E = E_MAX;

    float*  y;  cudaGetSymbolAddress((void**)&y, g_y);
    __half* z;  cudaGetSymbolAddress((void**)&z, g_z);
    int* deg;   cudaGetSymbolAddress((void**)&deg, g_deg);

    const int nB  = (N + 255) / 256;
    const int eB  = (E + 255) / 256;
    const int saB = (N + 255) / 256;
    const int gaB = (N * 32 + 255) / 256;     // warp per node
    const int gmB = (N + 127) / 128;

    // ---- CSR build (once; reused by all 3 layers)
    detect_kernel<<<1, 1>>>(ei);
    cudaMemsetAsync(deg, 0, N * sizeof(int));
    convert_kernel<<<eB, 256>>>(ei, E);
    scanA_kernel<<<saB, 256>>>(N);
    scanB_kernel<<<1, 256>>>(saB);
    scanC_kernel<<<nB, 256>>>(N);
    fill_kernel<<<eB, 256>>>(E);

    // ---- layer 1: z = feature@W1 ; y = relu(z_i + sum z_j + b1)
    gemm_kernel<128><<<gmB, 256>>>(feature, W1, z, N);
    gather128_kernel<<<gaB, 256>>>(z, b1, y, N);

    // ---- layer 2
    gemm_kernel<128><<<gmB, 256>>>(y, Wh, z, N);
    gather128_kernel<<<gaB, 256>>>(z, bh, y, N);

    // ---- layer 3 (+ fused log_softmax)
    gemm_kernel<64><<<gmB, 256>>>(y, Wo, z, N);
    gather64_lsm_kernel<<<gaB, 256>>>(z, bo, out, N);
}

// round 5
// speedup vs baseline: 1.3765x; 1.3765x over previous
#include <cuda_runtime.h>

#define N_NODES 50000
#define D 128
#define E_MAX 800000

// ---------------- device scratch (no allocation allowed) ----------------
__device__ float g_y[(size_t)N_NODES * D];    // gather outputs (activations)
__device__ float g_z[(size_t)N_NODES * D];    // GEMM outputs (gathered operand)
__device__ int   g_is64;
__device__ int   g_src[E_MAX];
__device__ int   g_dst[E_MAX];
__device__ int   g_perm[E_MAX];               // CSR: src ids grouped by dst
__device__ int   g_deg[N_NODES];
__device__ int   g_off[N_NODES];
__device__ int   g_cur[N_NODES];
__device__ int   g_bsum[256];

// ---------------- f32x2 packed-math helpers ----------------
__device__ __forceinline__ unsigned long long pack2(float a, float b) {
    unsigned long long r;
    asm("mov.b64 %0, {%1, %2};" : "=l"(r) : "f"(a), "f"(b));
    return r;
}
__device__ __forceinline__ void fma2(unsigned long long& d, unsigned long long a,
                                     unsigned long long b) {
    asm("fma.rn.f32x2 %0, %1, %2, %0;" : "+l"(d) : "l"(a), "l"(b));
}
__device__ __forceinline__ unsigned long long add2(unsigned long long a,
                                                   unsigned long long b) {
    unsigned long long r;
    asm("add.rn.f32x2 %0, %1, %2;" : "=l"(r) : "l"(a), "l"(b));
    return r;
}
__device__ __forceinline__ float2 unpack2(unsigned long long v) {
    float2 r;
    asm("mov.b64 {%0, %1}, %2;" : "=f"(r.x), "=f"(r.y) : "l"(v));
    return r;
}
__device__ __forceinline__ unsigned long long f4lo(float4 v) { return pack2(v.x, v.y); }
__device__ __forceinline__ unsigned long long f4hi(float4 v) { return pack2(v.z, v.w); }

// ---------------- dtype detection for edge_index ----------------
__global__ void detect_kernel(const void* __restrict__ ei) {
    if (blockIdx.x == 0 && threadIdx.x == 0) {
        const long long* p = (const long long*)ei;
        int ok = 1;
        #pragma unroll
        for (int i = 0; i < 32; i++) {
            long long v = p[i];
            if (v < 0 || v >= N_NODES) ok = 0;
        }
        g_is64 = ok;
    }
}

// ---------------- CSR build ----------------
__global__ void convert_kernel(const void* __restrict__ ei, int E) {
    int i = blockIdx.x * blockDim.x + threadIdx.x;
    if (i >= E) return;
    int s, d;
    if (g_is64) {
        const long long* p = (const long long*)ei;
        s = (int)__ldg(p + i);
        d = (int)__ldg(p + E + i);
    } else {
        const int* p = (const int*)ei;
        s = __ldg(p + i);
        d = __ldg(p + E + i);
    }
    g_src[i] = s;
    g_dst[i] = d;
    atomicAdd(&g_deg[d], 1);
}

__global__ void scanA_kernel(int n) {
    __shared__ int sh[8];
    int t = threadIdx.x, i = blockIdx.x * 256 + t;
    int v = (i < n) ? g_deg[i] : 0;
    int lane = t & 31, w = t >> 5;
    int x = v;
    #pragma unroll
    for (int o = 1; o < 32; o <<= 1) {
        int y = __shfl_up_sync(0xFFFFFFFFu, x, o);
        if (lane >= o) x += y;
    }
    if (lane == 31) sh[w] = x;
    __syncthreads();
    if (t < 8) {
        int s = sh[t];
        #pragma unroll
        for (int o = 1; o < 8; o <<= 1) {
            int y = __shfl_up_sync(0xFFu, s, o);
            if (t >= o) s += y;
        }
        sh[t] = s;
    }
    __syncthreads();
    int incl = x + (w ? sh[w - 1] : 0);
    if (i < n) g_off[i] = incl - v;
    if (t == 255) g_bsum[blockIdx.x] = incl;
}

__global__ void scanB_kernel(int nb) {
    __shared__ int sh[8];
    int t = threadIdx.x;
    int v = (t < nb) ? g_bsum[t] : 0;
    int lane = t & 31, w = t >> 5;
    int x = v;
    #pragma unroll
    for (int o = 1; o < 32; o <<= 1) {
        int y = __shfl_up_sync(0xFFFFFFFFu, x, o);
        if (lane >= o) x += y;
    }
    if (lane == 31) sh[w] = x;
    __syncthreads();
    if (t < 8) {
        int s = sh[t];
        #pragma unroll
        for (int o = 1; o < 8; o <<= 1) {
            int y = __shfl_up_sync(0xFFu, s, o);
            if (t >= o) s += y;
        }
        sh[t] = s;
    }
    __syncthreads();
    int incl = x + (w ? sh[w - 1] : 0);
    if (t < nb) g_bsum[t] = incl - v;
}

__global__ void scanC_kernel(int n) {
    int i = blockIdx.x * blockDim.x + threadIdx.x;
    if (i >= n) return;
    int o = g_off[i] + g_bsum[i >> 8];
    g_off[i] = o;
    g_cur[i] = o;
}

__global__ void fill_kernel(int E) {
    int i = blockIdx.x * blockDim.x + threadIdx.x;
    if (i >= E) return;
    int d = g_dst[i];
    int p = atomicAdd(&g_cur[d], 1);
    g_perm[p] = g_src[i];
}

// ---------------- SGEMM: z = A @ W  (fp32, no bias/act) ---------------------
// A: [N, 128]  W: [128, C]  BM=128, BN=C, BK=32, 256 threads, f32x2 packed FMA.
template <int C>
__global__ __launch_bounds__(256, 2)
void gemm_kernel(const float* __restrict__ A,
                 const float* __restrict__ W,
                 float* __restrict__ out,
                 int N) {
    constexpr int BM  = 128;
    constexpr int BK  = 32;
    constexpr int NCG = C / 8;
    constexpr int NRG = 256 / NCG;
    constexpr int RPT = BM / NRG;

    __shared__ __align__(16) float As[BK][BM];
    __shared__ __align__(16) float Ws[BK][C];

    const int tid  = threadIdx.x;
    const int tx   = tid % NCG;
    const int ty   = tid / NCG;
    const int row0 = blockIdx.x * BM;

    unsigned long long acc[RPT][4];
    #pragma unroll
    for (int i = 0; i < RPT; i++)
        #pragma unroll
        for (int j = 0; j < 4; j++) acc[i][j] = 0ULL;

    for (int kb = 0; kb < D; kb += BK) {
        #pragma unroll
        for (int t = tid; t < BM * BK / 4; t += 256) {
            int r = t & 127, c4 = t >> 7;
            float4 v = make_float4(0.f, 0.f, 0.f, 0.f);
            if (row0 + r < N)
                v = __ldg((const float4*)(A + (size_t)(row0 + r) * D + kb) + c4);
            As[c4 * 4 + 0][r] = v.x;
            As[c4 * 4 + 1][r] = v.y;
            As[c4 * 4 + 2][r] = v.z;
            As[c4 * 4 + 3][r] = v.w;
        }
        #pragma unroll
        for (int t = tid; t < BK * C / 4; t += 256)
            ((float4*)Ws)[t] = __ldg((const float4*)(W + (size_t)kb * C) + t);
        __syncthreads();

        #pragma unroll
        for (int k = 0; k < BK; k++) {
            float av[RPT];
            {
                const float4* ap = (const float4*)&As[k][ty * RPT];
                float4 a0 = ap[0];
                av[0] = a0.x; av[1] = a0.y; av[2] = a0.z; av[3] = a0.w;
                if (RPT == 8) {
                    float4 a1 = ap[1];
                    av[4] = a1.x; av[5] = a1.y; av[6] = a1.z; av[7] = a1.w;
                }
            }
            unsigned long long adup[RPT];
            #pragma unroll
            for (int i = 0; i < RPT; i++) adup[i] = pack2(av[i], av[i]);

            const unsigned long long* wrow = (const unsigned long long*)&Ws[k][tx * 8];
            unsigned long long w2[4];
            #pragma unroll
            for (int j = 0; j < 4; j++) w2[j] = wrow[j];

            #pragma unroll
            for (int i = 0; i < RPT; i++)
                #pragma unroll
                for (int j = 0; j < 4; j++)
                    fma2(acc[i][j], adup[i], w2[j]);
        }
        __syncthreads();
    }

    #pragma unroll
    for (int i = 0; i < RPT; i++) {
        int r = row0 + ty * RPT + i;
        if (r >= N) continue;
        float2 p0 = unpack2(acc[i][0]);
        float2 p1 = unpack2(acc[i][1]);
        float2 p2 = unpack2(acc[i][2]);
        float2 p3 = unpack2(acc[i][3]);
        float* o = out + (size_t)r * C + tx * 8;
        *(float4*)o       = make_float4(p0.x, p0.y, p1.x, p1.y);
        *((float4*)o + 1) = make_float4(p2.x, p2.y, p3.x, p3.y);
    }
}

// ---------- gather (128-wide): y[i] = relu(z[i] + sum_j z[j] + b) -----------
// Warp per node, lane holds float4 (cols 4l..4l+3). Direct broadcast index
// loads (no shfl), unroll x4 for MLP, packed f32x2 accumulation.
__global__ void gather128_kernel(const float* __restrict__ z,
                                 const float* __restrict__ bias,
                                 float* __restrict__ y, int N) {
    int node = (blockIdx.x * blockDim.x + threadIdx.x) >> 5;
    int lane = threadIdx.x & 31;
    if (node >= N) return;
    const float4* z4 = (const float4*)z;
    const int off = g_off[node];
    const int deg = g_deg[node];
    const int* __restrict__ p = g_perm + off;

    float4 a0 = __ldg(z4 + (size_t)node * 32 + lane);
    unsigned long long accL = f4lo(a0), accH = f4hi(a0);

    int t = 0;
    for (; t + 4 <= deg; t += 4) {
        int s0 = __ldg(p + t), s1 = __ldg(p + t + 1);
        int s2 = __ldg(p + t + 2), s3 = __ldg(p + t + 3);
        float4 v0 = __ldg(z4 + (size_t)s0 * 32 + lane);
        float4 v1 = __ldg(z4 + (size_t)s1 * 32 + lane);
        float4 v2 = __ldg(z4 + (size_t)s2 * 32 + lane);
        float4 v3 = __ldg(z4 + (size_t)s3 * 32 + lane);
        unsigned long long l01 = add2(f4lo(v0), f4lo(v1));
        unsigned long long l23 = add2(f4lo(v2), f4lo(v3));
        unsigned long long h01 = add2(f4hi(v0), f4hi(v1));
        unsigned long long h23 = add2(f4hi(v2), f4hi(v3));
        accL = add2(accL, add2(l01, l23));
        accH = add2(accH, add2(h01, h23));
    }
    for (; t < deg; t++) {
        int s = __ldg(p + t);
        float4 v = __ldg(z4 + (size_t)s * 32 + lane);
        accL = add2(accL, f4lo(v));
        accH = add2(accH, f4hi(v));
    }

    float2 lo = unpack2(accL), hi = unpack2(accH);
    float4 b = __ldg((const float4*)bias + lane);
    float4 r;
    r.x = fmaxf(lo.x + b.x, 0.f);
    r.y = fmaxf(lo.y + b.y, 0.f);
    r.z = fmaxf(hi.x + b.z, 0.f);
    r.w = fmaxf(hi.y + b.w, 0.f);
    ((float4*)y)[(size_t)node * 32 + lane] = r;
}

// ---------- gather (64-wide) + fused log_softmax -> d_out -------------------
// Warp per node, lane holds float2 (cols 2l, 2l+1).
__global__ void gather64_lsm_kernel(const float* __restrict__ z,
                                    const float* __restrict__ bias,
                                    float* __restrict__ out, int N) {
    int node = (blockIdx.x * blockDim.x + threadIdx.x) >> 5;
    int lane = threadIdx.x & 31;
    if (node >= N) return;
    const float2* z2 = (const float2*)z;
    const int off = g_off[node];
    const int deg = g_deg[node];
    const int* __restrict__ p = g_perm + off;

    float2 a = __ldg(z2 + (size_t)node * 32 + lane);
    unsigned long long acc = pack2(a.x, a.y);

    int t = 0;
    for (; t + 4 <= deg; t += 4) {
        int s0 = __ldg(p + t), s1 = __ldg(p + t + 1);
        int s2 = __ldg(p + t + 2), s3 = __ldg(p + t + 3);
        float2 v0 = __ldg(z2 + (size_t)s0 * 32 + lane);
        float2 v1 = __ldg(z2 + (size_t)s1 * 32 + lane);
        float2 v2 = __ldg(z2 + (size_t)s2 * 32 + lane);
        float2 v3 = __ldg(z2 + (size_t)s3 * 32 + lane);
        unsigned long long p01 = add2(pack2(v0.x, v0.y), pack2(v1.x, v1.y));
        unsigned long long p23 = add2(pack2(v2.x, v2.y), pack2(v3.x, v3.y));
        acc = add2(acc, add2(p01, p23));
    }
    for (; t < deg; t++) {
        int s = __ldg(p + t);
        float2 v = __ldg(z2 + (size_t)s * 32 + lane);
        acc = add2(acc, pack2(v.x, v.y));
    }

    float2 f = unpack2(acc);
    float2 b = __ldg((const float2*)bias + lane);
    f.x += b.x;
    f.y += b.y;

    float m = fmaxf(f.x, f.y);
    #pragma unroll
    for (int o = 16; o; o >>= 1) m = fmaxf(m, __shfl_xor_sync(0xFFFFFFFFu, m, o));
    float s = expf(f.x - m) + expf(f.y - m);
    #pragma unroll
    for (int o = 16; o; o >>= 1) s += __shfl_xor_sync(0xFFFFFFFFu, s, o);
    float l = m + logf(s);
    ((float2*)out)[(size_t)node * 32 + lane] = make_float2(f.x - l, f.y - l);
}

// ---------------- launch ----------------
extern "C" void kernel_launch(void* const* d_in, const int* in_sizes, int n_in,
                              void* d_out, int out_size) {
    const float* feature = (const float*)d_in[0];
    const void*  ei      = d_in[1];
    const float* W1      = (const float*)d_in[2];
    const float* b1      = (const float*)d_in[3];
    const float* Wh      = (const float*)d_in[4];
    const float* bh      = (const float*)d_in[5];
    const float* Wo      = (const float*)d_in[6];
    const float* bo      = (const float*)d_in[7];
    float* out = (float*)d_out;

    const int N = N_NODES;
    int E = in_sizes[1] / 2;
    if (E > E_MAX) E = E_MAX;

    float* y;   cudaGetSymbolAddress((void**)&y, g_y);
    float* z;   cudaGetSymbolAddress((void**)&z, g_z);
    int* deg;   cudaGetSymbolAddress((void**)&deg, g_deg);

    const int nB  = (N + 255) / 256;
    const int eB  = (E + 255) / 256;
    const int saB = (N + 255) / 256;
    const int gaB = (N * 32 + 255) / 256;     // warp per node
    const int gmB = (N + 127) / 128;

    // ---- CSR build (once; reused by all 3 layers)
    detect_kernel<<<1, 1>>>(ei);
    cudaMemsetAsync(deg, 0, N * sizeof(int));
    convert_kernel<<<eB, 256>>>(ei, E);
    scanA_kernel<<<saB, 256>>>(N);
    scanB_kernel<<<1, 256>>>(saB);
    scanC_kernel<<<nB, 256>>>(N);
    fill_kernel<<<eB, 256>>>(E);

    // ---- layer 1: z = feature@W1 ; y = relu(z_i + sum_j z_j + b1)
    gemm_kernel<128><<<gmB, 256>>>(feature, W1, z, N);
    gather128_kernel<<<gaB, 256>>>(z, b1, y, N);

    // ---- layer 2
    gemm_kernel<128><<<gmB, 256>>>(y, Wh, z, N);
    gather128_kernel<<<gaB, 256>>>(z, bh, y, N);

    // ---- layer 3 (+ fused log_softmax)
    gemm_kernel<64><<<gmB, 256>>>(y, Wo, z, N);
    gather64_lsm_kernel<<<gaB, 256>>>(z, bo, out, N);
}

// round 6
// speedup vs baseline: 1.4429x; 1.0482x over previous
#include <cuda_runtime.h>

#define N_NODES 50000
#define D 128
#define E_MAX 800000

// ---------------- device scratch (no allocation allowed) ----------------
__device__ float g_y[(size_t)N_NODES * D];    // gather outputs (activations)
__device__ float g_z[(size_t)N_NODES * D];    // GEMM outputs (gathered operand)
__device__ int   g_is64;
__device__ int   g_src[E_MAX];
__device__ int   g_dst[E_MAX];
__device__ int   g_perm[E_MAX];               // CSR: src ids grouped by dst
__device__ int   g_deg[N_NODES];
__device__ int   g_off[N_NODES];
__device__ int   g_cur[N_NODES];
__device__ int   g_bsum[256];

// ---------------- f32x2 packed-math helpers ----------------
__device__ __forceinline__ unsigned long long pack2(float a, float b) {
    unsigned long long r;
    asm("mov.b64 %0, {%1, %2};" : "=l"(r) : "f"(a), "f"(b));
    return r;
}
__device__ __forceinline__ void fma2(unsigned long long& d, unsigned long long a,
                                     unsigned long long b) {
    asm("fma.rn.f32x2 %0, %1, %2, %0;" : "+l"(d) : "l"(a), "l"(b));
}
__device__ __forceinline__ unsigned long long add2(unsigned long long a,
                                                   unsigned long long b) {
    unsigned long long r;
    asm("add.rn.f32x2 %0, %1, %2;" : "=l"(r) : "l"(a), "l"(b));
    return r;
}
__device__ __forceinline__ float2 unpack2(unsigned long long v) {
    float2 r;
    asm("mov.b64 {%0, %1}, %2;" : "=f"(r.x), "=f"(r.y) : "l"(v));
    return r;
}
__device__ __forceinline__ unsigned long long f4lo(float4 v) { return pack2(v.x, v.y); }
__device__ __forceinline__ unsigned long long f4hi(float4 v) { return pack2(v.z, v.w); }

// ---------------- init: zero degrees + dtype detect (fused) ----------------
__global__ void init_kernel(const void* __restrict__ ei) {
    int i = blockIdx.x * blockDim.x + threadIdx.x;
    if (i < N_NODES) g_deg[i] = 0;
    if (i == 0) {
        const long long* p = (const long long*)ei;
        int ok = 1;
        #pragma unroll
        for (int k = 0; k < 32; k++) {
            long long v = p[k];
            if (v < 0 || v >= N_NODES) ok = 0;
        }
        g_is64 = ok;
    }
}

// ---------------- CSR build ----------------
__global__ void convert_kernel(const void* __restrict__ ei, int E) {
    int i = blockIdx.x * blockDim.x + threadIdx.x;
    if (i >= E) return;
    int s, d;
    if (g_is64) {
        const long long* p = (const long long*)ei;
        s = (int)__ldg(p + i);
        d = (int)__ldg(p + E + i);
    } else {
        const int* p = (const int*)ei;
        s = __ldg(p + i);
        d = __ldg(p + E + i);
    }
    g_src[i] = s;
    g_dst[i] = d;
    atomicAdd(&g_deg[d], 1);
}

// per-256-block exclusive scan of deg -> off(partial), totals to bsum
__global__ void scanA_kernel(int n) {
    __shared__ int sh[8];
    int t = threadIdx.x, i = blockIdx.x * 256 + t;
    int v = (i < n) ? g_deg[i] : 0;
    int lane = t & 31, w = t >> 5;
    int x = v;
    #pragma unroll
    for (int o = 1; o < 32; o <<= 1) {
        int y = __shfl_up_sync(0xFFFFFFFFu, x, o);
        if (lane >= o) x += y;
    }
    if (lane == 31) sh[w] = x;
    __syncthreads();
    if (t < 8) {
        int s = sh[t];
        #pragma unroll
        for (int o = 1; o < 8; o <<= 1) {
            int y = __shfl_up_sync(0xFFu, s, o);
            if (t >= o) s += y;
        }
        sh[t] = s;
    }
    __syncthreads();
    int incl = x + (w ? sh[w - 1] : 0);
    if (i < n) g_off[i] = incl - v;
    if (t == 255) g_bsum[blockIdx.x] = incl;
}

// add prefix of block sums (each block reduces bsum[0..b) itself; scanB fused away)
__global__ void scanC_kernel(int n) {
    __shared__ int wsum[8];
    int b = blockIdx.x, t = threadIdx.x;
    int s = 0;
    for (int j = t; j < b; j += 256) s += g_bsum[j];
    #pragma unroll
    for (int o = 16; o; o >>= 1) s += __shfl_xor_sync(0xFFFFFFFFu, s, o);
    if ((t & 31) == 0) wsum[t >> 5] = s;
    __syncthreads();
    int base = 0;
    #pragma unroll
    for (int w = 0; w < 8; w++) base += wsum[w];
    int i = b * 256 + t;
    if (i < n) {
        int o = g_off[i] + base;
        g_off[i] = o;
        g_cur[i] = o;
    }
}

__global__ void fill_kernel(int E) {
    int i = blockIdx.x * blockDim.x + threadIdx.x;
    if (i >= E) return;
    int d = g_dst[i];
    int p = atomicAdd(&g_cur[d], 1);
    g_perm[p] = g_src[i];
}

// ---------------- SGEMM: z = A @ W  (fp32, software-pipelined) --------------
// A: [N, 128]  W: [128, C]  BM=128, BK=32, 256 threads, f32x2 packed FMA.
// Register-prefetch of next A/W chunk overlaps LDG latency with compute.
template <int C>
__global__ __launch_bounds__(256, 2)
void gemm_kernel(const float* __restrict__ A,
                 const float* __restrict__ W,
                 float* __restrict__ out,
                 int N) {
    constexpr int BM  = 128;
    constexpr int BK  = 32;
    constexpr int NCG = C / 8;
    constexpr int NRG = 256 / NCG;
    constexpr int RPT = BM / NRG;
    constexpr int NKB = D / BK;            // 4 chunks
    constexpr int A4  = BM * BK / 4 / 256; // 4 float4 per thread
    constexpr int W4  = BK * C / 4 / 256;  // 4 (C=128) or 2 (C=64)

    __shared__ __align__(16) float As[BK][BM];
    __shared__ __align__(16) float Ws[BK][C];

    const int tid  = threadIdx.x;
    const int tx   = tid % NCG;
    const int ty   = tid / NCG;
    const int row0 = blockIdx.x * BM;

    unsigned long long acc[RPT][4];
    #pragma unroll
    for (int i = 0; i < RPT; i++)
        #pragma unroll
        for (int j = 0; j < 4; j++) acc[i][j] = 0ULL;

    float4 aReg[A4], wReg[W4];

    // prefetch chunk 0
    #pragma unroll
    for (int j = 0; j < A4; j++) {
        int idx = tid + j * 256;
        int r = idx & 127, c4 = idx >> 7;
        aReg[j] = (row0 + r < N)
            ? __ldg((const float4*)(A + (size_t)(row0 + r) * D) + c4)
            : make_float4(0.f, 0.f, 0.f, 0.f);
    }
    #pragma unroll
    for (int j = 0; j < W4; j++)
        wReg[j] = __ldg((const float4*)W + tid + j * 256);

    for (int kb = 0; kb < NKB; kb++) {
        if (kb) __syncthreads();  // previous compute done before overwrite
        #pragma unroll
        for (int j = 0; j < A4; j++) {
            int idx = tid + j * 256;
            int r = idx & 127, c4 = idx >> 7;
            As[c4 * 4 + 0][r] = aReg[j].x;
            As[c4 * 4 + 1][r] = aReg[j].y;
            As[c4 * 4 + 2][r] = aReg[j].z;
            As[c4 * 4 + 3][r] = aReg[j].w;
        }
        #pragma unroll
        for (int j = 0; j < W4; j++)
            ((float4*)Ws)[tid + j * 256] = wReg[j];
        __syncthreads();

        if (kb + 1 < NKB) {   // issue next chunk's LDGs; latency hides under compute
            int kn = (kb + 1) * BK;
            #pragma unroll
            for (int j = 0; j < A4; j++) {
                int idx = tid + j * 256;
                int r = idx & 127, c4 = idx >> 7;
                aReg[j] = (row0 + r < N)
                    ? __ldg((const float4*)(A + (size_t)(row0 + r) * D + kn) + c4)
                    : make_float4(0.f, 0.f, 0.f, 0.f);
            }
            #pragma unroll
            for (int j = 0; j < W4; j++)
                wReg[j] = __ldg((const float4*)(W + (size_t)kn * C) + tid + j * 256);
        }

        #pragma unroll
        for (int k = 0; k < BK; k++) {
            float av[RPT];
            {
                const float4* ap = (const float4*)&As[k][ty * RPT];
                float4 a0 = ap[0];
                av[0] = a0.x; av[1] = a0.y; av[2] = a0.z; av[3] = a0.w;
                if (RPT == 8) {
                    float4 a1 = ap[1];
                    av[4] = a1.x; av[5] = a1.y; av[6] = a1.z; av[7] = a1.w;
                }
            }
            unsigned long long adup[RPT];
            #pragma unroll
            for (int i = 0; i < RPT; i++) adup[i] = pack2(av[i], av[i]);

            const unsigned long long* wrow = (const unsigned long long*)&Ws[k][tx * 8];
            unsigned long long w2[4];
            #pragma unroll
            for (int j = 0; j < 4; j++) w2[j] = wrow[j];

            #pragma unroll
            for (int i = 0; i < RPT; i++)
                #pragma unroll
                for (int j = 0; j < 4; j++)
                    fma2(acc[i][j], adup[i], w2[j]);
        }
    }

    #pragma unroll
    for (int i = 0; i < RPT; i++) {
        int r = row0 + ty * RPT + i;
        if (r >= N) continue;
        float2 p0 = unpack2(acc[i][0]);
        float2 p1 = unpack2(acc[i][1]);
        float2 p2 = unpack2(acc[i][2]);
        float2 p3 = unpack2(acc[i][3]);
        float* o = out + (size_t)r * C + tx * 8;
        *(float4*)o       = make_float4(p0.x, p0.y, p1.x, p1.y);
        *((float4*)o + 1) = make_float4(p2.x, p2.y, p3.x, p3.y);
    }
}

// ---------- gather (128-wide): y[i] = relu(z[i] + sum_j z[j] + b) -----------
__global__ void gather128_kernel(const float* __restrict__ z,
                                 const float* __restrict__ bias,
                                 float* __restrict__ y, int N) {
    int node = (blockIdx.x * blockDim.x + threadIdx.x) >> 5;
    int lane = threadIdx.x & 31;
    if (node >= N) return;
    const float4* z4 = (const float4*)z;
    const int off = g_off[node];
    const int deg = g_deg[node];
    const int* __restrict__ p = g_perm + off;

    float4 a0 = __ldg(z4 + (size_t)node * 32 + lane);
    unsigned long long accL = f4lo(a0), accH = f4hi(a0);

    int t = 0;
    for (; t + 4 <= deg; t += 4) {
        int s0 = __ldg(p + t), s1 = __ldg(p + t + 1);
        int s2 = __ldg(p + t + 2), s3 = __ldg(p + t + 3);
        float4 v0 = __ldg(z4 + (size_t)s0 * 32 + lane);
        float4 v1 = __ldg(z4 + (size_t)s1 * 32 + lane);
        float4 v2 = __ldg(z4 + (size_t)s2 * 32 + lane);
        float4 v3 = __ldg(z4 + (size_t)s3 * 32 + lane);
        unsigned long long l01 = add2(f4lo(v0), f4lo(v1));
        unsigned long long l23 = add2(f4lo(v2), f4lo(v3));
        unsigned long long h01 = add2(f4hi(v0), f4hi(v1));
        unsigned long long h23 = add2(f4hi(v2), f4hi(v3));
        accL = add2(accL, add2(l01, l23));
        accH = add2(accH, add2(h01, h23));
    }
    for (; t < deg; t++) {
        int s = __ldg(p + t);
        float4 v = __ldg(z4 + (size_t)s * 32 + lane);
        accL = add2(accL, f4lo(v));
        accH = add2(accH, f4hi(v));
    }

    float2 lo = unpack2(accL), hi = unpack2(accH);
    float4 b = __ldg((const float4*)bias + lane);
    float4 r;
    r.x = fmaxf(lo.x + b.x, 0.f);
    r.y = fmaxf(lo.y + b.y, 0.f);
    r.z = fmaxf(hi.x + b.z, 0.f);
    r.w = fmaxf(hi.y + b.w, 0.f);
    ((float4*)y)[(size_t)node * 32 + lane] = r;
}

// ---------- gather (64-wide) + fused log_softmax -> d_out -------------------
__global__ void gather64_lsm_kernel(const float* __restrict__ z,
                                    const float* __restrict__ bias,
                                    float* __restrict__ out, int N) {
    int node = (blockIdx.x * blockDim.x + threadIdx.x) >> 5;
    int lane = threadIdx.x & 31;
    if (node >= N) return;
    const float2* z2 = (const float2*)z;
    const int off = g_off[node];
    const int deg = g_deg[node];
    const int* __restrict__ p = g_perm + off;

    float2 a = __ldg(z2 + (size_t)node * 32 + lane);
    unsigned long long acc = pack2(a.x, a.y);

    int t = 0;
    for (; t + 4 <= deg; t += 4) {
        int s0 = __ldg(p + t), s1 = __ldg(p + t + 1);
        int s2 = __ldg(p + t + 2), s3 = __ldg(p + t + 3);
        float2 v0 = __ldg(z2 + (size_t)s0 * 32 + lane);
        float2 v1 = __ldg(z2 + (size_t)s1 * 32 + lane);
        float2 v2 = __ldg(z2 + (size_t)s2 * 32 + lane);
        float2 v3 = __ldg(z2 + (size_t)s3 * 32 + lane);
        unsigned long long p01 = add2(pack2(v0.x, v0.y), pack2(v1.x, v1.y));
        unsigned long long p23 = add2(pack2(v2.x, v2.y), pack2(v3.x, v3.y));
        acc = add2(acc, add2(p01, p23));
    }
    for (; t < deg; t++) {
        int s = __ldg(p + t);
        float2 v = __ldg(z2 + (size_t)s * 32 + lane);
        acc = add2(acc, pack2(v.x, v.y));
    }

    float2 f = unpack2(acc);
    float2 b = __ldg((const float2*)bias + lane);
    f.x += b.x;
    f.y += b.y;

    float m = fmaxf(f.x, f.y);
    #pragma unroll
    for (int o = 16; o; o >>= 1) m = fmaxf(m, __shfl_xor_sync(0xFFFFFFFFu, m, o));
    float s = expf(f.x - m) + expf(f.y - m);
    #pragma unroll
    for (int o = 16; o; o >>= 1) s += __shfl_xor_sync(0xFFFFFFFFu, s, o);
    float l = m + logf(s);
    ((float2*)out)[(size_t)node * 32 + lane] = make_float2(f.x - l, f.y - l);
}

// ---------------- launch ----------------
extern "C" void kernel_launch(void* const* d_in, const int* in_sizes, int n_in,
                              void* d_out, int out_size) {
    const float* feature = (const float*)d_in[0];
    const void*  ei      = d_in[1];
    const float* W1      = (const float*)d_in[2];
    const float* b1      = (const float*)d_in[3];
    const float* Wh      = (const float*)d_in[4];
    const float* bh      = (const float*)d_in[5];
    const float* Wo      = (const float*)d_in[6];
    const float* bo      = (const float*)d_in[7];
    float* out = (float*)d_out;

    const int N = N_NODES;
    int E = in_sizes[1] / 2;
    if (E > E_MAX) E = E_MAX;

    float* y;  cudaGetSymbolAddress((void**)&y, g_y);
    float* z;  cudaGetSymbolAddress((void**)&z, g_z);

    const int nB  = (N + 255) / 256;
    const int eB  = (E + 255) / 256;
    const int gaB = (N * 32 + 255) / 256;     // warp per node
    const int gmB = (N + 127) / 128;

    // lazily created side stream + events for capture fork/join (no device mem)
    static cudaStream_t s2 = nullptr;
    static cudaEvent_t evF = nullptr, evJ = nullptr;
    if (s2 == nullptr) {
        cudaStreamCreateWithFlags(&s2, cudaStreamNonBlocking);
        cudaEventCreateWithFlags(&evF, cudaEventDisableTiming);
        cudaEventCreateWithFlags(&evJ, cudaEventDisableTiming);
    }

    // ---- fork: CSR build on side stream, concurrent with GEMM-1 ----
    cudaEventRecord(evF, 0);
    cudaStreamWaitEvent(s2, evF, 0);

    init_kernel<<<nB, 256, 0, s2>>>(ei);
    convert_kernel<<<eB, 256, 0, s2>>>(ei, E);
    scanA_kernel<<<nB, 256, 0, s2>>>(N);
    scanC_kernel<<<nB, 256, 0, s2>>>(N);
    fill_kernel<<<eB, 256, 0, s2>>>(E);
    cudaEventRecord(evJ, s2);

    // main stream: gemm1 is independent of CSR
    gemm_kernel<128><<<gmB, 256>>>(feature, W1, z, N);

    // ---- join, then layers proceed serially ----
    cudaStreamWaitEvent(0, evJ, 0);
    gather128_kernel<<<gaB, 256>>>(z, b1, y, N);

    gemm_kernel<128><<<gmB, 256>>>(y, Wh, z, N);
    gather128_kernel<<<gaB, 256>>>(z, bh, y, N);

    gemm_kernel<64><<<gmB, 256>>>(y, Wo, z, N);
    gather64_lsm_kernel<<<gaB, 256>>>(z, bo, out, N);
}

// round 7
// speedup vs baseline: 2.0542x; 1.4237x over previous
#include <cuda_runtime.h>

#define N_NODES 50000
#define D 128
#define E_MAX 800000

// ---------------- device scratch (no allocation allowed) ----------------
__device__ float g_y[(size_t)N_NODES * D];    // gather outputs (activations)
__device__ float g_z[(size_t)N_NODES * D];    // GEMM outputs (gathered operand)
__device__ int   g_is64;
__device__ int   g_src[E_MAX];
__device__ int   g_dst[E_MAX];
__device__ int   g_perm[E_MAX];               // CSR: src ids grouped by dst
__device__ int   g_deg[N_NODES];
__device__ int   g_off[N_NODES];
__device__ int   g_cur[N_NODES];
__device__ int   g_bsum[256];

// ---------------- f32x2 packed helpers (gather accumulation) ----------------
__device__ __forceinline__ unsigned long long pack2(float a, float b) {
    unsigned long long r;
    asm("mov.b64 %0, {%1, %2};" : "=l"(r) : "f"(a), "f"(b));
    return r;
}
__device__ __forceinline__ unsigned long long add2(unsigned long long a,
                                                   unsigned long long b) {
    unsigned long long r;
    asm("add.rn.f32x2 %0, %1, %2;" : "=l"(r) : "l"(a), "l"(b));
    return r;
}
__device__ __forceinline__ float2 unpack2(unsigned long long v) {
    float2 r;
    asm("mov.b64 {%0, %1}, %2;" : "=f"(r.x), "=f"(r.y) : "l"(v));
    return r;
}
__device__ __forceinline__ unsigned long long f4lo(float4 v) { return pack2(v.x, v.y); }
__device__ __forceinline__ unsigned long long f4hi(float4 v) { return pack2(v.z, v.w); }

// ---------------- tf32 mma helpers ----------------
__device__ __forceinline__ unsigned to_tf32(float f) {
    unsigned r;
    asm("cvt.rna.tf32.f32 %0, %1;" : "=r"(r) : "f"(f));
    return r;
}
__device__ __forceinline__ void mma_tf32(float* c, unsigned a0, unsigned a1,
                                         unsigned a2, unsigned a3,
                                         unsigned b0, unsigned b1) {
    asm volatile(
        "mma.sync.aligned.m16n8k8.row.col.f32.tf32.tf32.f32 "
        "{%0,%1,%2,%3}, {%4,%5,%6,%7}, {%8,%9}, {%0,%1,%2,%3};"
        : "+f"(c[0]), "+f"(c[1]), "+f"(c[2]), "+f"(c[3])
        : "r"(a0), "r"(a1), "r"(a2), "r"(a3), "r"(b0), "r"(b1));
}

// ---------------- init: zero degrees + dtype detect (fused) ----------------
__global__ void init_kernel(const void* __restrict__ ei) {
    int i = blockIdx.x * blockDim.x + threadIdx.x;
    if (i < N_NODES) g_deg[i] = 0;
    if (i == 0) {
        const long long* p = (const long long*)ei;
        int ok = 1;
        #pragma unroll
        for (int k = 0; k < 32; k++) {
            long long v = p[k];
            if (v < 0 || v >= N_NODES) ok = 0;
        }
        g_is64 = ok;
    }
}

// ---------------- CSR build ----------------
__global__ void convert_kernel(const void* __restrict__ ei, int E) {
    int i = blockIdx.x * blockDim.x + threadIdx.x;
    if (i >= E) return;
    int s, d;
    if (g_is64) {
        const long long* p = (const long long*)ei;
        s = (int)__ldg(p + i);
        d = (int)__ldg(p + E + i);
    } else {
        const int* p = (const int*)ei;
        s = __ldg(p + i);
        d = __ldg(p + E + i);
    }
    g_src[i] = s;
    g_dst[i] = d;
    atomicAdd(&g_deg[d], 1);
}

__global__ void scanA_kernel(int n) {
    __shared__ int sh[8];
    int t = threadIdx.x, i = blockIdx.x * 256 + t;
    int v = (i < n) ? g_deg[i] : 0;
    int lane = t & 31, w = t >> 5;
    int x = v;
    #pragma unroll
    for (int o = 1; o < 32; o <<= 1) {
        int y = __shfl_up_sync(0xFFFFFFFFu, x, o);
        if (lane >= o) x += y;
    }
    if (lane == 31) sh[w] = x;
    __syncthreads();
    if (t < 8) {
        int s = sh[t];
        #pragma unroll
        for (int o = 1; o < 8; o <<= 1) {
            int y = __shfl_up_sync(0xFFu, s, o);
            if (t >= o) s += y;
        }
        sh[t] = s;
    }
    __syncthreads();
    int incl = x + (w ? sh[w - 1] : 0);
    if (i < n) g_off[i] = incl - v;
    if (t == 255) g_bsum[blockIdx.x] = incl;
}

__global__ void scanC_kernel(int n) {
    __shared__ int wsum[8];
    int b = blockIdx.x, t = threadIdx.x;
    int s = 0;
    for (int j = t; j < b; j += 256) s += g_bsum[j];
    #pragma unroll
    for (int o = 16; o; o >>= 1) s += __shfl_xor_sync(0xFFFFFFFFu, s, o);
    if ((t & 31) == 0) wsum[t >> 5] = s;
    __syncthreads();
    int base = 0;
    #pragma unroll
    for (int w = 0; w < 8; w++) base += wsum[w];
    int i = b * 256 + t;
    if (i < n) {
        int o = g_off[i] + base;
        g_off[i] = o;
        g_cur[i] = o;
    }
}

__global__ void fill_kernel(int E) {
    int i = blockIdx.x * blockDim.x + threadIdx.x;
    if (i >= E) return;
    int d = g_dst[i];
    int p = atomicAdd(&g_cur[d], 1);
    g_perm[p] = g_src[i];
}

// ---------------- tf32 tensor-core GEMM: z = A @ W ---------------------------
// A: [N,128]  W: [128,C]. BM=128, BK=32, 256 thr = 8 warps; warp w owns rows
// [16w,16w+16) and all C cols (C/8 n-tiles of m16n8k8). Smem staged with
// stride pad 8 (mod-32 = 8) so a/b LDS are bank-conflict-free.
template <int C>
__global__ __launch_bounds__(256, 2)
void gemm_tc_kernel(const float* __restrict__ A,
                    const float* __restrict__ W,
                    float* __restrict__ out,
                    int N) {
    constexpr int BM = 128;
    constexpr int BK = 32;
    constexpr int AS = BM + 8;          // 136
    constexpr int WS = C + 8;           // 136 / 72
    constexpr int NT = C / 8;           // n-tiles per warp (16 or 8)
    constexpr int W4 = BK * C / 4 / 256; // W float4 per thread (4 or 2)

    __shared__ unsigned As[BK * AS];    // tf32 bits, [k][row]
    __shared__ unsigned Ws[BK * WS];    // tf32 bits, [k][n]

    const int tid  = threadIdx.x;
    const int lane = tid & 31;
    const int warp = tid >> 5;
    const int row0 = blockIdx.x * BM;
    const int r0   = warp * 16 + (lane >> 2);   // a rows r0, r0+8
    const int kq   = lane & 3;
    const int nq   = lane >> 2;

    float acc[NT][4];
    #pragma unroll
    for (int i = 0; i < NT; i++)
        #pragma unroll
        for (int j = 0; j < 4; j++) acc[i][j] = 0.f;

    for (int kb0 = 0; kb0 < D; kb0 += BK) {
        if (kb0) __syncthreads();
        // stage A: BM*BK/4 = 1024 float4, 4 per thread, -> As[k][row] (tf32)
        #pragma unroll
        for (int j = 0; j < 4; j++) {
            int idx = tid + j * 256;
            int r = idx & 127, c4 = idx >> 7;
            float4 v = make_float4(0.f, 0.f, 0.f, 0.f);
            if (row0 + r < N)
                v = __ldg((const float4*)(A + (size_t)(row0 + r) * D + kb0) + c4);
            As[(c4 * 4 + 0) * AS + r] = to_tf32(v.x);
            As[(c4 * 4 + 1) * AS + r] = to_tf32(v.y);
            As[(c4 * 4 + 2) * AS + r] = to_tf32(v.z);
            As[(c4 * 4 + 3) * AS + r] = to_tf32(v.w);
        }
        // stage W -> Ws[k][n] (tf32)
        #pragma unroll
        for (int j = 0; j < W4; j++) {
            int idx = (tid + j * 256) * 4;
            int k = idx / C, n = idx % C;
            float4 v = __ldg((const float4*)(W + (size_t)(kb0 + k) * C + n));
            unsigned* w = &Ws[k * WS + n];
            w[0] = to_tf32(v.x);
            w[1] = to_tf32(v.y);
            w[2] = to_tf32(v.z);
            w[3] = to_tf32(v.w);
        }
        __syncthreads();

        #pragma unroll
        for (int ks = 0; ks < BK / 8; ks++) {
            int kk = ks * 8 + kq;
            unsigned a0 = As[kk * AS + r0];
            unsigned a1 = As[kk * AS + r0 + 8];
            unsigned a2 = As[(kk + 4) * AS + r0];
            unsigned a3 = As[(kk + 4) * AS + r0 + 8];
            #pragma unroll
            for (int nt = 0; nt < NT; nt++) {
                int n = nt * 8 + nq;
                unsigned b0 = Ws[kk * WS + n];
                unsigned b1 = Ws[(kk + 4) * WS + n];
                mma_tf32(acc[nt], a0, a1, a2, a3, b0, b1);
            }
        }
    }

    // epilogue: c0,c1 -> (r0, 2kq..2kq+1); c2,c3 -> (r0+8, same cols)
    int rA = row0 + r0, rB = rA + 8;
    #pragma unroll
    for (int nt = 0; nt < NT; nt++) {
        int cc = nt * 8 + 2 * kq;
        if (rA < N)
            *(float2*)(out + (size_t)rA * C + cc) = make_float2(acc[nt][0], acc[nt][1]);
        if (rB < N)
            *(float2*)(out + (size_t)rB * C + cc) = make_float2(acc[nt][2], acc[nt][3]);
    }
}

// ---------- gather (128-wide): y[i] = relu(z[i] + sum_j z[j] + b) -----------
__global__ void gather128_kernel(const float* __restrict__ z,
                                 const float* __restrict__ bias,
                                 float* __restrict__ y, int N) {
    int node = (blockIdx.x * blockDim.x + threadIdx.x) >> 5;
    int lane = threadIdx.x & 31;
    if (node >= N) return;
    const float4* z4 = (const float4*)z;
    const int off = g_off[node];
    const int deg = g_deg[node];
    const int* __restrict__ p = g_perm + off;

    float4 a0 = __ldg(z4 + (size_t)node * 32 + lane);
    unsigned long long accL = f4lo(a0), accH = f4hi(a0);

    int t = 0;
    for (; t + 4 <= deg; t += 4) {
        int s0 = __ldg(p + t), s1 = __ldg(p + t + 1);
        int s2 = __ldg(p + t + 2), s3 = __ldg(p + t + 3);
        float4 v0 = __ldg(z4 + (size_t)s0 * 32 + lane);
        float4 v1 = __ldg(z4 + (size_t)s1 * 32 + lane);
        float4 v2 = __ldg(z4 + (size_t)s2 * 32 + lane);
        float4 v3 = __ldg(z4 + (size_t)s3 * 32 + lane);
        unsigned long long l01 = add2(f4lo(v0), f4lo(v1));
        unsigned long long l23 = add2(f4lo(v2), f4lo(v3));
        unsigned long long h01 = add2(f4hi(v0), f4hi(v1));
        unsigned long long h23 = add2(f4hi(v2), f4hi(v3));
        accL = add2(accL, add2(l01, l23));
        accH = add2(accH, add2(h01, h23));
    }
    for (; t < deg; t++) {
        int s = __ldg(p + t);
        float4 v = __ldg(z4 + (size_t)s * 32 + lane);
        accL = add2(accL, f4lo(v));
        accH = add2(accH, f4hi(v));
    }

    float2 lo = unpack2(accL), hi = unpack2(accH);
    float4 b = __ldg((const float4*)bias + lane);
    float4 r;
    r.x = fmaxf(lo.x + b.x, 0.f);
    r.y = fmaxf(lo.y + b.y, 0.f);
    r.z = fmaxf(hi.x + b.z, 0.f);
    r.w = fmaxf(hi.y + b.w, 0.f);
    ((float4*)y)[(size_t)node * 32 + lane] = r;
}

// ---------- gather (64-wide) + fused log_softmax -> d_out -------------------
__global__ void gather64_lsm_kernel(const float* __restrict__ z,
                                    const float* __restrict__ bias,
                                    float* __restrict__ out, int N) {
    int node = (blockIdx.x * blockDim.x + threadIdx.x) >> 5;
    int lane = threadIdx.x & 31;
    if (node >= N) return;
    const float2* z2 = (const float2*)z;
    const int off = g_off[node];
    const int deg = g_deg[node];
    const int* __restrict__ p = g_perm + off;

    float2 a = __ldg(z2 + (size_t)node * 32 + lane);
    unsigned long long acc = pack2(a.x, a.y);

    int t = 0;
    for (; t + 4 <= deg; t += 4) {
        int s0 = __ldg(p + t), s1 = __ldg(p + t + 1);
        int s2 = __ldg(p + t + 2), s3 = __ldg(p + t + 3);
        float2 v0 = __ldg(z2 + (size_t)s0 * 32 + lane);
        float2 v1 = __ldg(z2 + (size_t)s1 * 32 + lane);
        float2 v2 = __ldg(z2 + (size_t)s2 * 32 + lane);
        float2 v3 = __ldg(z2 + (size_t)s3 * 32 + lane);
        unsigned long long p01 = add2(pack2(v0.x, v0.y), pack2(v1.x, v1.y));
        unsigned long long p23 = add2(pack2(v2.x, v2.y), pack2(v3.x, v3.y));
        acc = add2(acc, add2(p01, p23));
    }
    for (; t < deg; t++) {
        int s = __ldg(p + t);
        float2 v = __ldg(z2 + (size_t)s * 32 + lane);
        acc = add2(acc, pack2(v.x, v.y));
    }

    float2 f = unpack2(acc);
    float2 b = __ldg((const float2*)bias + lane);
    f.x += b.x;
    f.y += b.y;

    float m = fmaxf(f.x, f.y);
    #pragma unroll
    for (int o = 16; o; o >>= 1) m = fmaxf(m, __shfl_xor_sync(0xFFFFFFFFu, m, o));
    float s = expf(f.x - m) + expf(f.y - m);
    #pragma unroll
    for (int o = 16; o; o >>= 1) s += __shfl_xor_sync(0xFFFFFFFFu, s, o);
    float l = m + logf(s);
    ((float2*)out)[(size_t)node * 32 + lane] = make_float2(f.x - l, f.y - l);
}

// ---------------- launch ----------------
extern "C" void kernel_launch(void* const* d_in, const int* in_sizes, int n_in,
                              void* d_out, int out_size) {
    const float* feature = (const float*)d_in[0];
    const void*  ei      = d_in[1];
    const float* W1      = (const float*)d_in[2];
    const float* b1      = (const float*)d_in[3];
    const float* Wh      = (const float*)d_in[4];
    const float* bh      = (const float*)d_in[5];
    const float* Wo      = (const float*)d_in[6];
    const float* bo      = (const float*)d_in[7];
    float* out = (float*)d_out;

    const int N = N_NODES;
    int E = in_sizes[1] / 2;
    if (E > E_MAX) E = E_MAX;

    float* y;  cudaGetSymbolAddress((void**)&y, g_y);
    float* z;  cudaGetSymbolAddress((void**)&z, g_z);

    const int nB  = (N + 255) / 256;
    const int eB  = (E + 255) / 256;
    const int gaB = (N * 32 + 255) / 256;     // warp per node
    const int gmB = (N + 127) / 128;

    // lazily created side stream + events for capture fork/join (no device mem)
    static cudaStream_t s2 = nullptr;
    static cudaEvent_t evF = nullptr, evJ = nullptr;
    if (s2 == nullptr) {
        cudaStreamCreateWithFlags(&s2, cudaStreamNonBlocking);
        cudaEventCreateWithFlags(&evF, cudaEventDisableTiming);
        cudaEventCreateWithFlags(&evJ, cudaEventDisableTiming);
    }

    // ---- fork: CSR build on side stream, concurrent with GEMM-1 ----
    cudaEventRecord(evF, 0);
    cudaStreamWaitEvent(s2, evF, 0);

    init_kernel<<<nB, 256, 0, s2>>>(ei);
    convert_kernel<<<eB, 256, 0, s2>>>(ei, E);
    scanA_kernel<<<nB, 256, 0, s2>>>(N);
    scanC_kernel<<<nB, 256, 0, s2>>>(N);
    fill_kernel<<<eB, 256, 0, s2>>>(E);
    cudaEventRecord(evJ, s2);

    // main stream: gemm1 is independent of CSR
    gemm_tc_kernel<128><<<gmB, 256>>>(feature, W1, z, N);

    // ---- join, then layers proceed serially ----
    cudaStreamWaitEvent(0, evJ, 0);
    gather128_kernel<<<gaB, 256>>>(z, b1, y, N);

    gemm_tc_kernel<128><<<gmB, 256>>>(y, Wh, z, N);
    gather128_kernel<<<gaB, 256>>>(z, bh, y, N);

    gemm_tc_kernel<64><<<gmB, 256>>>(y, Wo, z, N);
    gather64_lsm_kernel<<<gaB, 256>>>(z, bo, out, N);
}

// round 8
// speedup vs baseline: 2.1900x; 1.0661x over previous
#include <cuda_runtime.h>
#include <cuda_fp16.h>

#define N_NODES 50000
#define D 128
#define E_MAX 800000

typedef unsigned long long ull;

// ---------------- device scratch (no allocation allowed) ----------------
__device__ float  g_y[(size_t)N_NODES * D];   // gather outputs (fp32 activations)
__device__ __half g_z[(size_t)N_NODES * D];   // GEMM outputs (fp16, gathered)
__device__ int    g_is64;
__device__ int    g_src[E_MAX];
__device__ int    g_dst[E_MAX];
__device__ int    g_perm[E_MAX];              // CSR: src ids grouped by dst
__device__ int    g_deg[N_NODES];
__device__ int    g_off[N_NODES];
__device__ int    g_cur[N_NODES];
__device__ int    g_bsum[256];

// ---------------- f32x2 packed helpers ----------------
__device__ __forceinline__ ull pack2(float a, float b) {
    ull r;
    asm("mov.b64 %0, {%1, %2};" : "=l"(r) : "f"(a), "f"(b));
    return r;
}
__device__ __forceinline__ ull add2(ull a, ull b) {
    ull r;
    asm("add.rn.f32x2 %0, %1, %2;" : "=l"(r) : "l"(a), "l"(b));
    return r;
}
__device__ __forceinline__ float2 unpack2(ull v) {
    float2 r;
    asm("mov.b64 {%0, %1}, %2;" : "=f"(r.x), "=f"(r.y) : "l"(v));
    return r;
}

// accumulate 8 halves (uint4) into 4 packed f32x2 accumulators
__device__ __forceinline__ void hacc(ull& a0, ull& a1, ull& a2, ull& a3, uint4 v) {
    float2 f0 = __half22float2(*(const __half2*)&v.x);
    float2 f1 = __half22float2(*(const __half2*)&v.y);
    float2 f2 = __half22float2(*(const __half2*)&v.z);
    float2 f3 = __half22float2(*(const __half2*)&v.w);
    a0 = add2(a0, pack2(f0.x, f0.y));
    a1 = add2(a1, pack2(f1.x, f1.y));
    a2 = add2(a2, pack2(f2.x, f2.y));
    a3 = add2(a3, pack2(f3.x, f3.y));
}

// ---------------- tf32 mma helpers ----------------
__device__ __forceinline__ unsigned to_tf32(float f) {
    unsigned r;
    asm("cvt.rna.tf32.f32 %0, %1;" : "=r"(r) : "f"(f));
    return r;
}
__device__ __forceinline__ void mma_tf32(float* c, unsigned a0, unsigned a1,
                                         unsigned a2, unsigned a3,
                                         unsigned b0, unsigned b1) {
    asm volatile(
        "mma.sync.aligned.m16n8k8.row.col.f32.tf32.tf32.f32 "
        "{%0,%1,%2,%3}, {%4,%5,%6,%7}, {%8,%9}, {%0,%1,%2,%3};"
        : "+f"(c[0]), "+f"(c[1]), "+f"(c[2]), "+f"(c[3])
        : "r"(a0), "r"(a1), "r"(a2), "r"(a3), "r"(b0), "r"(b1));
}

// ---------------- init: zero degrees + dtype detect (fused) ----------------
__global__ void init_kernel(const void* __restrict__ ei) {
    int i = blockIdx.x * blockDim.x + threadIdx.x;
    if (i < N_NODES) g_deg[i] = 0;
    if (i == 0) {
        const long long* p = (const long long*)ei;
        int ok = 1;
        #pragma unroll
        for (int k = 0; k < 32; k++) {
            long long v = p[k];
            if (v < 0 || v >= N_NODES) ok = 0;
        }
        g_is64 = ok;
    }
}

// ---------------- CSR build ----------------
__global__ void convert_kernel(const void* __restrict__ ei, int E) {
    int i = blockIdx.x * blockDim.x + threadIdx.x;
    if (i >= E) return;
    int s, d;
    if (g_is64) {
        const long long* p = (const long long*)ei;
        s = (int)__ldg(p + i);
        d = (int)__ldg(p + E + i);
    } else {
        const int* p = (const int*)ei;
        s = __ldg(p + i);
        d = __ldg(p + E + i);
    }
    g_src[i] = s;
    g_dst[i] = d;
    atomicAdd(&g_deg[d], 1);
}

__global__ void scanA_kernel(int n) {
    __shared__ int sh[8];
    int t = threadIdx.x, i = blockIdx.x * 256 + t;
    int v = (i < n) ? g_deg[i] : 0;
    int lane = t & 31, w = t >> 5;
    int x = v;
    #pragma unroll
    for (int o = 1; o < 32; o <<= 1) {
        int y = __shfl_up_sync(0xFFFFFFFFu, x, o);
        if (lane >= o) x += y;
    }
    if (lane == 31) sh[w] = x;
    __syncthreads();
    if (t < 8) {
        int s = sh[t];
        #pragma unroll
        for (int o = 1; o < 8; o <<= 1) {
            int y = __shfl_up_sync(0xFFu, s, o);
            if (t >= o) s += y;
        }
        sh[t] = s;
    }
    __syncthreads();
    int incl = x + (w ? sh[w - 1] : 0);
    if (i < n) g_off[i] = incl - v;
    if (t == 255) g_bsum[blockIdx.x] = incl;
}

__global__ void scanC_kernel(int n) {
    __shared__ int wsum[8];
    int b = blockIdx.x, t = threadIdx.x;
    int s = 0;
    for (int j = t; j < b; j += 256) s += g_bsum[j];
    #pragma unroll
    for (int o = 16; o; o >>= 1) s += __shfl_xor_sync(0xFFFFFFFFu, s, o);
    if ((t & 31) == 0) wsum[t >> 5] = s;
    __syncthreads();
    int base = 0;
    #pragma unroll
    for (int w = 0; w < 8; w++) base += wsum[w];
    int i = b * 256 + t;
    if (i < n) {
        int o = g_off[i] + base;
        g_off[i] = o;
        g_cur[i] = o;
    }
}

__global__ void fill_kernel(int E) {
    int i = blockIdx.x * blockDim.x + threadIdx.x;
    if (i >= E) return;
    int d = g_dst[i];
    int p = atomicAdd(&g_cur[d], 1);
    g_perm[p] = g_src[i];
}

// ---------------- tf32 tensor-core GEMM: z = A @ W (fp16 out) ---------------
template <int C>
__global__ __launch_bounds__(256, 2)
void gemm_tc_kernel(const float* __restrict__ A,
                    const float* __restrict__ W,
                    __half* __restrict__ out,
                    int N) {
    constexpr int BM = 128;
    constexpr int BK = 32;
    constexpr int AS = BM + 8;
    constexpr int WS = C + 8;
    constexpr int NT = C / 8;
    constexpr int W4 = BK * C / 4 / 256;

    __shared__ unsigned As[BK * AS];
    __shared__ unsigned Ws[BK * WS];

    const int tid  = threadIdx.x;
    const int lane = tid & 31;
    const int warp = tid >> 5;
    const int row0 = blockIdx.x * BM;
    const int r0   = warp * 16 + (lane >> 2);
    const int kq   = lane & 3;
    const int nq   = lane >> 2;

    float acc[NT][4];
    #pragma unroll
    for (int i = 0; i < NT; i++)
        #pragma unroll
        for (int j = 0; j < 4; j++) acc[i][j] = 0.f;

    for (int kb0 = 0; kb0 < D; kb0 += BK) {
        if (kb0) __syncthreads();
        #pragma unroll
        for (int j = 0; j < 4; j++) {
            int idx = tid + j * 256;
            int r = idx & 127, c4 = idx >> 7;
            float4 v = make_float4(0.f, 0.f, 0.f, 0.f);
            if (row0 + r < N)
                v = __ldg((const float4*)(A + (size_t)(row0 + r) * D + kb0) + c4);
            As[(c4 * 4 + 0) * AS + r] = to_tf32(v.x);
            As[(c4 * 4 + 1) * AS + r] = to_tf32(v.y);
            As[(c4 * 4 + 2) * AS + r] = to_tf32(v.z);
            As[(c4 * 4 + 3) * AS + r] = to_tf32(v.w);
        }
        #pragma unroll
        for (int j = 0; j < W4; j++) {
            int idx = (tid + j * 256) * 4;
            int k = idx / C, n = idx % C;
            float4 v = __ldg((const float4*)(W + (size_t)(kb0 + k) * C + n));
            unsigned* w = &Ws[k * WS + n];
            w[0] = to_tf32(v.x);
            w[1] = to_tf32(v.y);
            w[2] = to_tf32(v.z);
            w[3] = to_tf32(v.w);
        }
        __syncthreads();

        #pragma unroll
        for (int ks = 0; ks < BK / 8; ks++) {
            int kk = ks * 8 + kq;
            unsigned a0 = As[kk * AS + r0];
            unsigned a1 = As[kk * AS + r0 + 8];
            unsigned a2 = As[(kk + 4) * AS + r0];
            unsigned a3 = As[(kk + 4) * AS + r0 + 8];
            #pragma unroll
            for (int nt = 0; nt < NT; nt++) {
                int n = nt * 8 + nq;
                unsigned b0 = Ws[kk * WS + n];
                unsigned b1 = Ws[(kk + 4) * WS + n];
                mma_tf32(acc[nt], a0, a1, a2, a3, b0, b1);
            }
        }
    }

    int rA = row0 + r0, rB = rA + 8;
    #pragma unroll
    for (int nt = 0; nt < NT; nt++) {
        int cc = nt * 8 + 2 * kq;
        if (rA < N)
            *(__half2*)(out + (size_t)rA * C + cc) = __floats2half2_rn(acc[nt][0], acc[nt][1]);
        if (rB < N)
            *(__half2*)(out + (size_t)rB * C + cc) = __floats2half2_rn(acc[nt][2], acc[nt][3]);
    }
}

// ---------- gather (128-wide, fp16 z): y[i] = relu(z[i] + sum_j z[j] + b) ---
// Warp per node. Row = 256B = 16 uint4; 16 lanes per row -> 2 neighbors per
// wavefront, x4 unroll = 8 in flight. fp32 packed accumulation; one 64-bit
// shfl fold between half-warps at the end.
__global__ void gather128h_kernel(const __half* __restrict__ z,
                                  const float* __restrict__ bias,
                                  float* __restrict__ y, int N) {
    int node = (blockIdx.x * blockDim.x + threadIdx.x) >> 5;
    int lane = threadIdx.x & 31;
    if (node >= N) return;
    const uint4* z4 = (const uint4*)z;          // 16 per row
    const int off = g_off[node];
    const int deg = g_deg[node];
    const int* __restrict__ p = g_perm + off;
    const int hw = lane >> 4;                   // 0/1: neighbor parity
    const int cg = lane & 15;                   // col group (8 halves)

    ull a0 = 0, a1 = 0, a2 = 0, a3 = 0;
    if (hw == 0)
        hacc(a0, a1, a2, a3, __ldg(z4 + (size_t)node * 16 + cg));

    int t = 0;
    for (; t + 8 <= deg; t += 8) {
        int i = t + hw;
        int s0 = __ldg(p + i),     s1 = __ldg(p + i + 2);
        int s2 = __ldg(p + i + 4), s3 = __ldg(p + i + 6);
        uint4 v0 = __ldg(z4 + (size_t)s0 * 16 + cg);
        uint4 v1 = __ldg(z4 + (size_t)s1 * 16 + cg);
        uint4 v2 = __ldg(z4 + (size_t)s2 * 16 + cg);
        uint4 v3 = __ldg(z4 + (size_t)s3 * 16 + cg);
        hacc(a0, a1, a2, a3, v0);
        hacc(a0, a1, a2, a3, v1);
        hacc(a0, a1, a2, a3, v2);
        hacc(a0, a1, a2, a3, v3);
    }
    for (; t + 2 <= deg; t += 2) {
        int s = __ldg(p + t + hw);
        hacc(a0, a1, a2, a3, __ldg(z4 + (size_t)s * 16 + cg));
    }
    if (t < deg && hw == 0) {
        int s = __ldg(p + t);
        hacc(a0, a1, a2, a3, __ldg(z4 + (size_t)s * 16 + cg));
    }

    // fold half-warps (lane l += lane l+16; same cg)
    a0 = add2(a0, __shfl_down_sync(0xFFFFFFFFu, a0, 16));
    a1 = add2(a1, __shfl_down_sync(0xFFFFFFFFu, a1, 16));
    a2 = add2(a2, __shfl_down_sync(0xFFFFFFFFu, a2, 16));
    a3 = add2(a3, __shfl_down_sync(0xFFFFFFFFu, a3, 16));

    if (hw == 0) {
        float2 f0 = unpack2(a0), f1 = unpack2(a1);
        float2 f2 = unpack2(a2), f3 = unpack2(a3);
        float4 b0 = __ldg((const float4*)bias + cg * 2);
        float4 b1 = __ldg((const float4*)bias + cg * 2 + 1);
        float4 r0, r1;
        r0.x = fmaxf(f0.x + b0.x, 0.f); r0.y = fmaxf(f0.y + b0.y, 0.f);
        r0.z = fmaxf(f1.x + b0.z, 0.f); r0.w = fmaxf(f1.y + b0.w, 0.f);
        r1.x = fmaxf(f2.x + b1.x, 0.f); r1.y = fmaxf(f2.y + b1.y, 0.f);
        r1.z = fmaxf(f3.x + b1.z, 0.f); r1.w = fmaxf(f3.y + b1.w, 0.f);
        float* o = y + (size_t)node * 128 + cg * 8;
        *(float4*)o       = r0;
        *((float4*)o + 1) = r1;
    }
}

// ---------- gather (64-wide, fp16 z) + fused log_softmax -> d_out -----------
// Row = 128B = 8 uint4; 8 lanes per row -> 4 neighbors per wavefront.
__global__ void gather64h_lsm_kernel(const __half* __restrict__ z,
                                     const float* __restrict__ bias,
                                     float* __restrict__ out, int N) {
    int node = (blockIdx.x * blockDim.x + threadIdx.x) >> 5;
    int lane = threadIdx.x & 31;
    if (node >= N) return;
    const uint4* z4 = (const uint4*)z;          // 8 per row
    const int off = g_off[node];
    const int deg = g_deg[node];
    const int* __restrict__ p = g_perm + off;
    const int q  = lane >> 3;                   // 0..3: neighbor sub-slot
    const int cg = lane & 7;                    // col group (8 halves)

    ull a0 = 0, a1 = 0, a2 = 0, a3 = 0;
    if (q == 0)
        hacc(a0, a1, a2, a3, __ldg(z4 + (size_t)node * 8 + cg));

    int t = 0;
    for (; t + 8 <= deg; t += 8) {
        int s0 = __ldg(p + t + q), s1 = __ldg(p + t + q + 4);
        uint4 v0 = __ldg(z4 + (size_t)s0 * 8 + cg);
        uint4 v1 = __ldg(z4 + (size_t)s1 * 8 + cg);
        hacc(a0, a1, a2, a3, v0);
        hacc(a0, a1, a2, a3, v1);
    }
    for (; t + 4 <= deg; t += 4) {
        int s = __ldg(p + t + q);
        hacc(a0, a1, a2, a3, __ldg(z4 + (size_t)s * 8 + cg));
    }
    int rem = deg - t;
    if (q < rem) {
        int s = __ldg(p + t + q);
        hacc(a0, a1, a2, a3, __ldg(z4 + (size_t)s * 8 + cg));
    }

    // fold 4 sub-slots: +16 then +8
    a0 = add2(a0, __shfl_down_sync(0xFFFFFFFFu, a0, 16));
    a1 = add2(a1, __shfl_down_sync(0xFFFFFFFFu, a1, 16));
    a2 = add2(a2, __shfl_down_sync(0xFFFFFFFFu, a2, 16));
    a3 = add2(a3, __shfl_down_sync(0xFFFFFFFFu, a3, 16));
    a0 = add2(a0, __shfl_down_sync(0xFFFFFFFFu, a0, 8));
    a1 = add2(a1, __shfl_down_sync(0xFFFFFFFFu, a1, 8));
    a2 = add2(a2, __shfl_down_sync(0xFFFFFFFFu, a2, 8));
    a3 = add2(a3, __shfl_down_sync(0xFFFFFFFFu, a3, 8));

    // lanes 0..7 hold the full row (8 cols each); bias + log_softmax
    float2 f0 = unpack2(a0), f1 = unpack2(a1);
    float2 f2 = unpack2(a2), f3 = unpack2(a3);
    float4 b0 = __ldg((const float4*)bias + cg * 2);
    float4 b1 = __ldg((const float4*)bias + cg * 2 + 1);
    float v[8];
    v[0] = f0.x + b0.x; v[1] = f0.y + b0.y; v[2] = f1.x + b0.z; v[3] = f1.y + b0.w;
    v[4] = f2.x + b1.x; v[5] = f2.y + b1.y; v[6] = f3.x + b1.z; v[7] = f3.y + b1.w;

    float m = v[0];
    #pragma unroll
    for (int j = 1; j < 8; j++) m = fmaxf(m, v[j]);
    #pragma unroll
    for (int o = 4; o; o >>= 1) m = fmaxf(m, __shfl_xor_sync(0xFFFFFFFFu, m, o));
    float s = 0.f;
    #pragma unroll
    for (int j = 0; j < 8; j++) s += expf(v[j] - m);
    #pragma unroll
    for (int o = 4; o; o >>= 1) s += __shfl_xor_sync(0xFFFFFFFFu, s, o);
    float l = m + logf(s);

    if (q == 0) {
        float* o = out + (size_t)node * 64 + cg * 8;
        *(float4*)o       = make_float4(v[0] - l, v[1] - l, v[2] - l, v[3] - l);
        *((float4*)o + 1) = make_float4(v[4] - l, v[5] - l, v[6] - l, v[7] - l);
    }
}

// ---------------- launch ----------------
extern "C" void kernel_launch(void* const* d_in, const int* in_sizes, int n_in,
                              void* d_out, int out_size) {
    const float* feature = (const float*)d_in[0];
    const void*  ei      = d_in[1];
    const float* W1      = (const float*)d_in[2];
    const float* b1      = (const float*)d_in[3];
    const float* Wh      = (const float*)d_in[4];
    const float* bh      = (const float*)d_in[5];
    const float* Wo      = (const float*)d_in[6];
    const float* bo      = (const float*)d_in[7];
    float* out = (float*)d_out;

    const int N = N_NODES;
    int E = in_sizes[1] / 2;
    if (E > E_MAX) E = E_MAX;

    float*  y;  cudaGetSymbolAddress((void**)&y, g_y);
    __half* z;  cudaGetSymbolAddress((void**)&z, g_z);

    const int nB  = (N + 255) / 256;
    const int eB  = (E + 255) / 256;
    const int gaB = (N * 32 + 255) / 256;     // warp per node
    const int gmB = (N + 127) / 128;

    static cudaStream_t s2 = nullptr;
    static cudaEvent_t evF = nullptr, evJ = nullptr;
    if (s2 == nullptr) {
        cudaStreamCreateWithFlags(&s2, cudaStreamNonBlocking);
        cudaEventCreateWithFlags(&evF, cudaEventDisableTiming);
        cudaEventCreateWithFlags(&evJ, cudaEventDisableTiming);
    }

    // ---- fork: CSR build on side stream, concurrent with GEMM-1 ----
    cudaEventRecord(evF, 0);
    cudaStreamWaitEvent(s2, evF, 0);

    init_kernel<<<nB, 256, 0, s2>>>(ei);
    convert_kernel<<<eB, 256, 0, s2>>>(ei, E);
    scanA_kernel<<<nB, 256, 0, s2>>>(N);
    scanC_kernel<<<nB, 256, 0, s2>>>(N);
    fill_kernel<<<eB, 256, 0, s2>>>(E);
    cudaEventRecord(evJ, s2);

    gemm_tc_kernel<128><<<gmB, 256>>>(feature, W1, z, N);

    cudaStreamWaitEvent(0, evJ, 0);
    gather128h_kernel<<<gaB, 256>>>(z, b1, y, N);

    gemm_tc_kernel<128><<<gmB, 256>>>(y, Wh, z, N);
    gather128h_kernel<<<gaB, 256>>>(z, bh, y, N);

    gemm_tc_kernel<64><<<gmB, 256>>>(y, Wo, z, N);
    gather64h_lsm_kernel<<<gaB, 256>>>(z, bo, out, N);
}